// round 14
// baseline (speedup 1.0000x reference)
#include <cuda_runtime.h>
#include <math.h>

#define NB 32
#define NL 128
#define NCH 20
#define NFILT 200
#define NHID 256
#define DPAD 512
#define NSS 6
#define NLAB 8
#define NTOK 4096
#define REC_CTAS 64

// ---------------- device scratch (no allocation allowed) -------------------
__device__ float g_inp[NTOK * DPAD];        // [l*32+b][512] (500 used, 12 pad)
__device__ float g_wih0p[2048 * DPAD];      // padded w_ih0 [2048][512]
__device__ float g_gx[NTOK * 2048];         // input projections
__device__ float g_h[2 * 2 * NHID * NB];    // [parity][dir][j][b]
__device__ float g_out0[NTOK * DPAD];
__device__ float g_out1[NTOK * DPAD];
__device__ float g_crfwT[NLAB * NSS * DPAD];
__device__ float g_em[NLAB * NB * NL * NSS];
__device__ float g_loss[NLAB * NB];
__device__ unsigned g_bar_arrive;
__device__ unsigned g_bar_gen;

// ---------------- word embeddings ------------------------------------------
__global__ void embed_kernel(const int* __restrict__ iv, const int* __restrict__ ov,
                             const float* __restrict__ wtab, const float* __restrict__ otab) {
    int idx = blockIdx.x * blockDim.x + threadIdx.x;
    if (idx >= NTOK * 300) return;
    int d = idx % 300, tok = idx / 300;
    int b = tok >> 7, l = tok & 127;
    float v = wtab[iv[tok] * 300 + d];
    int oi = ov[tok];
    if (oi != 0) v += otab[oi * 300 + d];
    g_inp[(l * NB + b) * DPAD + d] = v;
}

__global__ void pad_inp_kernel() {
    int idx = blockIdx.x * blockDim.x + threadIdx.x;
    if (idx >= NTOK * 12) return;
    g_inp[(idx / 12) * DPAD + 500 + (idx % 12)] = 0.f;
}

__global__ void pad_w_kernel(const float* __restrict__ w) {
    int idx = blockIdx.x * blockDim.x + threadIdx.x;
    if (idx >= 2048 * DPAD) return;
    int n = idx >> 9, k = idx & 511;
    g_wih0p[idx] = (k < 500) ? w[n * 500 + k] : 0.f;
}

// ---------------- char CNN + maxpool + sigmoid -----------------------------
__global__ __launch_bounds__(256) void charconv_kernel(
    const int* __restrict__ chars, const float* __restrict__ ctab,
    const float* __restrict__ cw, const float* __restrict__ cb) {
    __shared__ float ch[24 * 50];           // rows c+2, zero padded
    int bx = blockIdx.x;                    // b*128 + l
    int b = bx >> 7, l = bx & 127;
    int tid = threadIdx.x;
    for (int i = tid; i < 24 * 50; i += 256) {
        int row = i / 50, e = i % 50;
        int c = row - 2;
        float v = 0.f;
        if (c >= 0 && c < NCH) {
            int ci = chars[bx * NCH + c];
            if (ci != 0) v = ctab[ci * 50 + e];
        }
        ch[i] = v;
    }
    __syncthreads();
    int f = tid;
    if (f < NFILT) {
        float acc[22];
#pragma unroll
        for (int t = 0; t < 22; t++) acc[t] = 0.f;
        const float* wf = cw + f * 150;
        for (int e = 0; e < 50; e++) {
            float w0 = wf[e * 3 + 0], w1 = wf[e * 3 + 1], w2 = wf[e * 3 + 2];
            float cr[24];
#pragma unroll
            for (int c2 = 0; c2 < 24; c2++) cr[c2] = ch[c2 * 50 + e];
#pragma unroll
            for (int t = 0; t < 22; t++)
                acc[t] = fmaf(w0, cr[t], fmaf(w1, cr[t + 1], fmaf(w2, cr[t + 2], acc[t])));
        }
        float mx = acc[0];
#pragma unroll
        for (int t = 1; t < 22; t++) mx = fmaxf(mx, acc[t]);
        mx += cb[f];
        g_inp[(l * NB + b) * DPAD + 300 + f] = 1.f / (1.f + expf(-mx));
    }
}

// ---------------- input-projection GEMM: C[4096][2048] = A[4096][512]*Bw^T --
__global__ __launch_bounds__(256) void gemm_kernel(
    int layer, const float* __restrict__ Bw_ext, const float* __restrict__ bias) {
    __shared__ __align__(16) float As[8][128];
    __shared__ __align__(16) float Bs[8][128];
    const float* A  = layer ? g_out0 : g_inp;
    const float* Bw = layer ? Bw_ext : g_wih0p;
    float* C = g_gx;
    int m0 = blockIdx.y * 128, n0 = blockIdx.x * 128;
    int tid = threadIdx.x;
    int lm = tid >> 1, lk = (tid & 1) * 4;
    int ty = tid >> 4, tx = tid & 15;
    float acc[8][8];
#pragma unroll
    for (int i = 0; i < 8; i++)
#pragma unroll
        for (int j = 0; j < 8; j++) acc[i][j] = 0.f;
    const float* Ap = A + (m0 + lm) * 512 + lk;
    const float* Bp = Bw + (n0 + lm) * 512 + lk;
    float4 av = *(const float4*)Ap;
    float4 bv = *(const float4*)Bp;
    for (int k0 = 0; k0 < 512; k0 += 8) {
        __syncthreads();
        As[lk + 0][lm] = av.x; As[lk + 1][lm] = av.y;
        As[lk + 2][lm] = av.z; As[lk + 3][lm] = av.w;
        Bs[lk + 0][lm] = bv.x; Bs[lk + 1][lm] = bv.y;
        Bs[lk + 2][lm] = bv.z; Bs[lk + 3][lm] = bv.w;
        if (k0 + 8 < 512) {
            av = *(const float4*)(Ap + k0 + 8);
            bv = *(const float4*)(Bp + k0 + 8);
        }
        __syncthreads();
#pragma unroll
        for (int k = 0; k < 8; k++) {
            float a[8], bb[8];
            *(float4*)(a)      = *(const float4*)&As[k][ty * 8];
            *(float4*)(a + 4)  = *(const float4*)&As[k][ty * 8 + 4];
            *(float4*)(bb)     = *(const float4*)&Bs[k][tx * 8];
            *(float4*)(bb + 4) = *(const float4*)&Bs[k][tx * 8 + 4];
#pragma unroll
            for (int i = 0; i < 8; i++)
#pragma unroll
                for (int j = 0; j < 8; j++) acc[i][j] = fmaf(a[i], bb[j], acc[i][j]);
        }
    }
    float bb2[8];
#pragma unroll
    for (int j = 0; j < 8; j++) bb2[j] = bias[n0 + tx * 8 + j];
#pragma unroll
    for (int i = 0; i < 8; i++) {
        float* Cp = C + (m0 + ty * 8 + i) * 2048 + n0 + tx * 8;
        float4 v0 = make_float4(acc[i][0] + bb2[0], acc[i][1] + bb2[1],
                                acc[i][2] + bb2[2], acc[i][3] + bb2[3]);
        float4 v1 = make_float4(acc[i][4] + bb2[4], acc[i][5] + bb2[5],
                                acc[i][6] + bb2[6], acc[i][7] + bb2[7]);
        *(float4*)Cp = v0;
        *(float4*)(Cp + 4) = v1;
    }
}

// ---------------- persistent BiLSTM layer (grid barrier) --------------------
#define GRIDBAR()                                                              \
    do {                                                                       \
        __syncthreads();                                                       \
        if (tid == 0) {                                                        \
            genT++;                                                            \
            unsigned aa = atomicAdd(&g_bar_arrive, 1u);                        \
            if (aa == REC_CTAS - 1) {                                          \
                g_bar_arrive = 0u;                                             \
                __threadfence();                                               \
                atomicExch(&g_bar_gen, genT);                                  \
            } else {                                                           \
                while (*((volatile unsigned*)&g_bar_gen) != genT) {            \
                    __nanosleep(64);                                           \
                }                                                              \
            }                                                                  \
        }                                                                      \
        __syncthreads();                                                       \
    } while (0)

__global__ __launch_bounds__(256) void lstm_kernel(
    int layer, const float* __restrict__ whh, const float* __restrict__ maskp) {
    extern __shared__ float sm[];
    float* wS = sm;            // [256][32] k-major weight slice
    float* hS = sm + 8192;     // [256][32] h_prev (k-major, b minor)
    float* gS = sm + 16384;    // [32][33] partial gates
    const float* gx = g_gx;
    float* out = layer ? g_out1 : g_out0;
    int tid = threadIdx.x;
    int dir = blockIdx.x >> 5;
    int j0 = (blockIdx.x & 31) * 8;
    // load w_hh slice: rows {gt*256 + j0 + jj}, transposed into smem
    for (int idx = tid; idx < 8192; idx += 256) {
        int r = idx >> 8, k = idx & 255;
        int row = (r >> 3) * 256 + j0 + (r & 7);
        wS[k * 32 + r] = whh[dir * 262144 + row * 256 + k];
    }
    int jj = tid >> 5, b2 = tid & 31;
    int r = tid >> 3, bg = tid & 7;
    float cReg = 0.f, hReg = 0.f;
    g_h[dir * 8192 + (j0 + jj) * 32 + b2] = 0.f;   // parity-0 init
    unsigned genT = 0;
    if (tid == 0) genT = *((volatile unsigned*)&g_bar_gen);
    __threadfence();
    GRIDBAR();
    for (int t = 0; t < 128; t++) {
        int p = t & 1;
        int l = dir ? (127 - t) : t;
        // prefetch gx + mask (independent of h exchange)
        const float* gxp = gx + (l * 32 + b2) * 2048 + dir * 1024 + j0 + jj;
        float pgi = gxp[0], pgf = gxp[256], pgg = gxp[512], pgo = gxp[768];
        float mval = maskp[b2 * 128 + l];
        // stage h_prev into smem
        const float4* hsrc = (const float4*)(g_h + (p * 2 + dir) * 8192);
        float4* hdst = (float4*)hS;
        for (int i = tid; i < 2048; i += 256) hdst[i] = hsrc[i];
        __syncthreads();
        // 32 gate-rows x 32 batch matvec over K=256
        float a0 = 0.f, a1 = 0.f, a2 = 0.f, a3 = 0.f;
        const float* wp = wS + r;
        const float* hp = hS + bg * 4;
#pragma unroll 8
        for (int k = 0; k < 256; k++) {
            float w = wp[k * 32];
            float4 h4 = *(const float4*)(hp + k * 32);
            a0 = fmaf(w, h4.x, a0);
            a1 = fmaf(w, h4.y, a1);
            a2 = fmaf(w, h4.z, a2);
            a3 = fmaf(w, h4.w, a3);
        }
        float* gp = gS + r * 33 + bg * 4;
        gp[0] = a0; gp[1] = a1; gp[2] = a2; gp[3] = a3;
        __syncthreads();
        // elementwise LSTM for (j0+jj, b2)
        float gi = gS[(0  + jj) * 33 + b2] + pgi;
        float gf = gS[(8  + jj) * 33 + b2] + pgf;
        float gg = gS[(16 + jj) * 33 + b2] + pgg;
        float go = gS[(24 + jj) * 33 + b2] + pgo;
        float ii = 1.f / (1.f + expf(-gi));
        float ff = 1.f / (1.f + expf(-gf));
        float g2 = tanhf(gg);
        float oo = 1.f / (1.f + expf(-go));
        float cn = ff * cReg + ii * g2;
        float hn = oo * tanhf(cn);
        hReg = mval * hn + (1.f - mval) * hReg;
        cReg = mval * cn + (1.f - mval) * cReg;
        out[(l * 32 + b2) * 512 + dir * 256 + j0 + jj] = hReg;
        g_h[((1 - p) * 2 + dir) * 8192 + (j0 + jj) * 32 + b2] = hReg;
        __threadfence();
        GRIDBAR();
    }
}

// ---------------- CRF emission weights transpose ---------------------------
__global__ void crfwT_kernel(const float* __restrict__ cw) {
    int idx = blockIdx.x * blockDim.x + threadIdx.x;
    if (idx >= NLAB * NSS * DPAD) return;
    int d = idx & 511;
    int n = (idx >> 9) % 6;
    int k = idx / (512 * 6);
    g_crfwT[idx] = cw[k * 3072 + d * 6 + n];
}

// ---------------- emissions ------------------------------------------------
__global__ __launch_bounds__(64) void em_kernel(const float* __restrict__ crfb) {
    __shared__ __align__(16) float rowS[512];
    int bx = blockIdx.x;                 // row = l*32+b
    int l = bx >> 5, b = bx & 31;
    int tid = threadIdx.x;
    const float4* src = (const float4*)(g_out1 + bx * 512);
    float4* dst = (float4*)rowS;
    for (int i = tid; i < 128; i += 64) dst[i] = src[i];
    __syncthreads();
    if (tid < 48) {
        int k = tid / 6, n = tid % 6;
        const float* wp = g_crfwT + (k * 6 + n) * 512;
        float s = 0.f;
        for (int d = 0; d < 512; d += 4) {
            float4 w4 = *(const float4*)(wp + d);
            float4 r4 = *(const float4*)(rowS + d);
            s = fmaf(w4.x, r4.x, s); s = fmaf(w4.y, r4.y, s);
            s = fmaf(w4.z, r4.z, s); s = fmaf(w4.w, r4.w, s);
        }
        g_em[k * 24576 + b * 768 + l * 6 + n] = s + crfb[k * 6 + n];
    }
}

// ---------------- CRF forward + gold score ---------------------------------
__global__ __launch_bounds__(32) void crf_kernel(const float* __restrict__ trans,
                                                 const int* __restrict__ target,
                                                 const float* __restrict__ maskp) {
    __shared__ float trS[36];
    int k = blockIdx.x, b = threadIdx.x;
    for (int i = b; i < 36; i += 32) trS[i] = trans[k * 36 + i];
    __syncthreads();
    const float* emp = g_em + k * 24576 + b * 768;
    const int* tg = target + k * 4096 + b * 128;
    const float* mp = maskp + b * 128;
    float alpha[6];
#pragma unroll
    for (int n = 0; n < 6; n++) alpha[n] = emp[n];
    float score = emp[tg[0]] * mp[0];
    int py = tg[0];
    for (int l = 1; l < 128; l++) {
        float m = mp[l];
        const float* e = emp + l * 6;
        int y = tg[l];
        score += (e[y] + trS[py * 6 + y]) * m;
        py = y;
        float na[6];
#pragma unroll
        for (int j = 0; j < 6; j++) {
            float x0 = alpha[0] + trS[j];
            float x1 = alpha[1] + trS[6 + j];
            float x2 = alpha[2] + trS[12 + j];
            float x3 = alpha[3] + trS[18 + j];
            float x4 = alpha[4] + trS[24 + j];
            float x5 = alpha[5] + trS[30 + j];
            float mx = fmaxf(fmaxf(fmaxf(x0, x1), fmaxf(x2, x3)), fmaxf(x4, x5));
            float s = __expf(x0 - mx) + __expf(x1 - mx) + __expf(x2 - mx) +
                      __expf(x3 - mx) + __expf(x4 - mx) + __expf(x5 - mx);
            na[j] = mx + __logf(s) + e[j];
        }
#pragma unroll
        for (int j = 0; j < 6; j++) alpha[j] = m * na[j] + (1.f - m) * alpha[j];
    }
    float mx = alpha[0];
#pragma unroll
    for (int n = 1; n < 6; n++) mx = fmaxf(mx, alpha[n]);
    float s = 0.f;
#pragma unroll
    for (int n = 0; n < 6; n++) s += __expf(alpha[n] - mx);
    g_loss[k * 32 + b] = mx + __logf(s) - score;
}

// ---------------- final reduction ------------------------------------------
__global__ void reduce_kernel(float* out) {
    __shared__ float red[256];
    int tid = threadIdx.x;
    red[tid] = g_loss[tid];
    __syncthreads();
    for (int s = 128; s > 0; s >>= 1) {
        if (tid < s) red[tid] += red[tid + s];
        __syncthreads();
    }
    if (tid == 0) out[0] = red[0] * (1.f / 32.f);
}

// ---------------------------------------------------------------------------
extern "C" void kernel_launch(void* const* d_in, const int* in_sizes, int n_in,
                              void* d_out, int out_size) {
    (void)in_sizes; (void)n_in; (void)out_size;
    const int*   iv    = (const int*)d_in[0];
    const int*   ov    = (const int*)d_in[1];
    const int*   chars = (const int*)d_in[2];
    const int*   target= (const int*)d_in[3];
    const float* mask  = (const float*)d_in[4];
    const float* wtab  = (const float*)d_in[5];
    const float* otab  = (const float*)d_in[6];
    const float* ctab  = (const float*)d_in[7];
    const float* convw = (const float*)d_in[8];
    const float* convb = (const float*)d_in[9];
    const float* wih0  = (const float*)d_in[10];
    const float* whh0  = (const float*)d_in[11];
    const float* b0    = (const float*)d_in[12];
    const float* wih1  = (const float*)d_in[13];
    const float* whh1  = (const float*)d_in[14];
    const float* b1    = (const float*)d_in[15];
    const float* crfw  = (const float*)d_in[16];
    const float* crfb  = (const float*)d_in[17];
    const float* crftr = (const float*)d_in[18];

    const int SMEM_LSTM = (8192 + 8192 + 32 * 33) * 4;  // 69760 B
    cudaFuncSetAttribute(lstm_kernel, cudaFuncAttributeMaxDynamicSharedMemorySize, SMEM_LSTM);

    embed_kernel<<<(NTOK * 300 + 255) / 256, 256>>>(iv, ov, wtab, otab);
    pad_inp_kernel<<<(NTOK * 12 + 255) / 256, 256>>>();
    pad_w_kernel<<<(2048 * DPAD + 255) / 256, 256>>>(wih0);
    charconv_kernel<<<NTOK, 256>>>(chars, ctab, convw, convb);
    crfwT_kernel<<<(NLAB * NSS * DPAD + 255) / 256, 256>>>(crfw);

    dim3 gg(16, 32);
    gemm_kernel<<<gg, 256>>>(0, (const float*)0, b0);
    lstm_kernel<<<REC_CTAS, 256, SMEM_LSTM>>>(0, whh0, mask);
    gemm_kernel<<<gg, 256>>>(1, wih1, b1);
    lstm_kernel<<<REC_CTAS, 256, SMEM_LSTM>>>(1, whh1, mask);

    em_kernel<<<NTOK, 64>>>(crfb);
    crf_kernel<<<NLAB, 32>>>(crftr, target, mask);
    reduce_kernel<<<1, 256>>>((float*)d_out);
}

// round 15
// speedup vs baseline: 1.9484x; 1.9484x over previous
#include <cuda_runtime.h>
#include <math.h>

#define NB 32
#define NL 128
#define NCH 20
#define NFILT 200
#define NHID 256
#define DPAD 512
#define NSS 6
#define NLAB 8
#define NTOK 4096
#define REC_CTAS 128

// ---------------- device scratch (no allocation allowed) -------------------
__device__ float g_inp[NTOK * DPAD];        // [l*32+b][512] (500 used, 12 pad)
__device__ float g_wih0p[2048 * DPAD];      // padded w_ih0 [2048][512]
__device__ float g_gx[NTOK * 2048];         // input projections
__device__ float g_h[2 * 2 * NHID * NB];    // [parity][dir][j][b]
__device__ float g_out0[NTOK * DPAD];
__device__ float g_out1[NTOK * DPAD];
__device__ float g_T[100 * 3 * NFILT];      // char conv table [ci][k][f]
__device__ float g_crfwT[NLAB * NSS * DPAD];
__device__ float g_em[NLAB * NB * NL * NSS];
__device__ float g_loss[NLAB * NB];
__device__ unsigned g_bar_arrive;
__device__ unsigned g_bar_gen;

// ---------------- word embeddings ------------------------------------------
__global__ void embed_kernel(const int* __restrict__ iv, const int* __restrict__ ov,
                             const float* __restrict__ wtab, const float* __restrict__ otab) {
    int idx = blockIdx.x * blockDim.x + threadIdx.x;
    if (idx >= NTOK * 300) return;
    int d = idx % 300, tok = idx / 300;
    int b = tok >> 7, l = tok & 127;
    float v = wtab[iv[tok] * 300 + d];
    int oi = ov[tok];
    if (oi != 0) v += otab[oi * 300 + d];
    g_inp[(l * NB + b) * DPAD + d] = v;
}

__global__ void pad_inp_kernel() {
    int idx = blockIdx.x * blockDim.x + threadIdx.x;
    if (idx >= NTOK * 12) return;
    g_inp[(idx / 12) * DPAD + 500 + (idx % 12)] = 0.f;
}

__global__ void pad_w_kernel(const float* __restrict__ w) {
    int idx = blockIdx.x * blockDim.x + threadIdx.x;
    if (idx >= 2048 * DPAD) return;
    int n = idx >> 9, k = idx & 511;
    g_wih0p[idx] = (k < 500) ? w[n * 500 + k] : 0.f;
}

// ---------------- char conv table precompute -------------------------------
// T[ci][k][f] = sum_e ctab[ci][e] * cw[f][e][k]   (T[0][*][*] = 0)
__global__ __launch_bounds__(600) void chartab_kernel(
    const float* __restrict__ ctab, const float* __restrict__ cw) {
    __shared__ float ce[50];
    int ci = blockIdx.x;
    int tid = threadIdx.x;
    if (tid < 50) ce[tid] = ctab[ci * 50 + tid];
    __syncthreads();
    int k = tid / NFILT, f = tid % NFILT;   // tid in [0,600)
    float s = 0.f;
    const float* wp = cw + f * 150 + k;
#pragma unroll 10
    for (int e = 0; e < 50; e++) s = fmaf(ce[e], wp[e * 3], s);
    g_T[ci * 600 + k * NFILT + f] = (ci == 0) ? 0.f : s;
}

// ---------------- char CNN via table + maxpool + sigmoid -------------------
__global__ __launch_bounds__(256) void charconv_kernel(
    const int* __restrict__ chars, const float* __restrict__ cb) {
    __shared__ int ci[NCH];
    int bx = blockIdx.x;                    // b*128 + l
    int b = bx >> 7, l = bx & 127;
    int tid = threadIdx.x;
    if (tid < NCH) ci[tid] = chars[bx * NCH + tid];
    __syncthreads();
    int f = tid;
    if (f < NFILT) {
        float best = -1e30f;
#pragma unroll
        for (int p = 0; p < 22; p++) {
            float s = 0.f;
#pragma unroll
            for (int k = 0; k < 3; k++) {
                int c = p + k - 2;
                if (c >= 0 && c < NCH)
                    s += g_T[ci[c] * 600 + k * NFILT + f];
            }
            best = fmaxf(best, s);
        }
        best += cb[f];
        g_inp[(l * NB + b) * DPAD + 300 + f] = 1.f / (1.f + expf(-best));
    }
}

// ---------------- input-projection GEMM (double-buffered) -------------------
// C[4096][2048] = A[4096][512] * Bw^T  (+bias)
__global__ __launch_bounds__(256) void gemm_kernel(
    int layer, const float* __restrict__ Bw_ext, const float* __restrict__ bias) {
    __shared__ __align__(16) float As[2][8][128];
    __shared__ __align__(16) float Bs[2][8][128];
    const float* A  = layer ? g_out0 : g_inp;
    const float* Bw = layer ? Bw_ext : g_wih0p;
    float* C = g_gx;
    int m0 = blockIdx.y * 128, n0 = blockIdx.x * 128;
    int tid = threadIdx.x;
    int lm = tid >> 1, lk = (tid & 1) * 4;
    int ty = tid >> 4, tx = tid & 15;
    float acc[8][8];
#pragma unroll
    for (int i = 0; i < 8; i++)
#pragma unroll
        for (int j = 0; j < 8; j++) acc[i][j] = 0.f;
    const float* Ap = A + (m0 + lm) * 512 + lk;
    const float* Bp = Bw + (n0 + lm) * 512 + lk;
    float4 av = *(const float4*)Ap;
    float4 bv = *(const float4*)Bp;
    As[0][lk + 0][lm] = av.x; As[0][lk + 1][lm] = av.y;
    As[0][lk + 2][lm] = av.z; As[0][lk + 3][lm] = av.w;
    Bs[0][lk + 0][lm] = bv.x; Bs[0][lk + 1][lm] = bv.y;
    Bs[0][lk + 2][lm] = bv.z; Bs[0][lk + 3][lm] = bv.w;
    __syncthreads();
    for (int k0 = 0; k0 < 512; k0 += 8) {
        int p = (k0 >> 3) & 1;
        bool more = (k0 + 8) < 512;
        if (more) {
            av = *(const float4*)(Ap + k0 + 8);
            bv = *(const float4*)(Bp + k0 + 8);
        }
#pragma unroll
        for (int k = 0; k < 8; k++) {
            float a[8], bb[8];
            *(float4*)(a)      = *(const float4*)&As[p][k][ty * 8];
            *(float4*)(a + 4)  = *(const float4*)&As[p][k][ty * 8 + 4];
            *(float4*)(bb)     = *(const float4*)&Bs[p][k][tx * 8];
            *(float4*)(bb + 4) = *(const float4*)&Bs[p][k][tx * 8 + 4];
#pragma unroll
            for (int i = 0; i < 8; i++)
#pragma unroll
                for (int j = 0; j < 8; j++) acc[i][j] = fmaf(a[i], bb[j], acc[i][j]);
        }
        if (more) {
            int q = p ^ 1;
            As[q][lk + 0][lm] = av.x; As[q][lk + 1][lm] = av.y;
            As[q][lk + 2][lm] = av.z; As[q][lk + 3][lm] = av.w;
            Bs[q][lk + 0][lm] = bv.x; Bs[q][lk + 1][lm] = bv.y;
            Bs[q][lk + 2][lm] = bv.z; Bs[q][lk + 3][lm] = bv.w;
            __syncthreads();
        }
    }
    float bb2[8];
#pragma unroll
    for (int j = 0; j < 8; j++) bb2[j] = bias[n0 + tx * 8 + j];
#pragma unroll
    for (int i = 0; i < 8; i++) {
        float* Cp = C + (m0 + ty * 8 + i) * 2048 + n0 + tx * 8;
        float4 v0 = make_float4(acc[i][0] + bb2[0], acc[i][1] + bb2[1],
                                acc[i][2] + bb2[2], acc[i][3] + bb2[3]);
        float4 v1 = make_float4(acc[i][4] + bb2[4], acc[i][5] + bb2[5],
                                acc[i][6] + bb2[6], acc[i][7] + bb2[7]);
        *(float4*)Cp = v0;
        *(float4*)(Cp + 4) = v1;
    }
}

// ---------------- persistent BiLSTM layer (grid barrier) --------------------
#define GRIDBAR()                                                              \
    do {                                                                       \
        __syncthreads();                                                       \
        if (tid == 0) {                                                        \
            genT++;                                                            \
            unsigned aa = atomicAdd(&g_bar_arrive, 1u);                        \
            if (aa == REC_CTAS - 1) {                                          \
                g_bar_arrive = 0u;                                             \
                __threadfence();                                               \
                atomicExch(&g_bar_gen, genT);                                  \
            } else {                                                           \
                while (*((volatile unsigned*)&g_bar_gen) != genT) {            \
                    __nanosleep(32);                                           \
                }                                                              \
            }                                                                  \
        }                                                                      \
        __syncthreads();                                                       \
    } while (0)

// 128 CTAs: dir (2) x slice (64 of 4 hidden units = 16 gate rows).
// smem: wS [256k][16r] 16KB | hS [256k][32b] 32KB | pS [8kc][512] 16KB
__global__ __launch_bounds__(256) void lstm_kernel(
    int layer, const float* __restrict__ whh, const float* __restrict__ maskp) {
    extern __shared__ float sm[];
    float* wS = sm;
    float* hS = sm + 4096;
    float* pS = sm + 4096 + 8192;
    float* out = layer ? g_out1 : g_out0;
    int tid = threadIdx.x;
    int dir = blockIdx.x >> 6;
    int j0 = (blockIdx.x & 63) * 4;
    // load w_hh slice (16 gate rows) into k-major smem
    for (int idx = tid; idx < 4096; idx += 256) {
        int r = idx >> 8, k = idx & 255;                       // r=gate*4+jl
        int row = (r >> 2) * 256 + j0 + (r & 3);
        wS[k * 16 + r] = __ldg(&whh[dir * 262144 + row * 256 + k]);
    }
    int kc = tid >> 5, lane = tid & 31;
    int rg = lane >> 3, bg = lane & 7;
    int j = tid >> 5, b = tid & 31;       // elementwise mapping (tid<128)
    float cReg = 0.f, hReg = 0.f;
    if (tid < 128)
        g_h[dir * 8192 + (j0 + j) * 32 + b] = 0.f;             // parity-0 init
    unsigned genT = 0;
    if (tid == 0) genT = *((volatile unsigned*)&g_bar_gen);
    __threadfence();
    GRIDBAR();
    for (int t = 0; t < 128; t++) {
        int p = t & 1;
        int l = dir ? (127 - t) : t;
        float pgi = 0.f, pgf = 0.f, pgg = 0.f, pgo = 0.f, mval = 0.f;
        if (tid < 128) {   // prefetch gx + mask (independent of h)
            const float* gxp = g_gx + (l * 32 + b) * 2048 + dir * 1024 + j0 + j;
            pgi = gxp[0]; pgf = gxp[256]; pgg = gxp[512]; pgo = gxp[768];
            mval = maskp[b * 128 + l];
        }
        // stage h_prev (L2-coherent path)
        {
            const float4* hsrc = (const float4*)(g_h + (p * 2 + dir) * 8192);
            float4* hdst = (float4*)hS;
#pragma unroll
            for (int i = 0; i < 8; i++)
                hdst[tid + i * 256] = __ldcg(hsrc + tid + i * 256);
        }
        __syncthreads();
        // 16 rows x 32 batch x K=256, 8-way K-split, 4x4 outer product
        {
            float4 a0 = {0,0,0,0}, a1 = {0,0,0,0}, a2 = {0,0,0,0}, a3 = {0,0,0,0};
            const float* wp = wS + kc * 32 * 16 + rg * 4;
            const float* hp = hS + kc * 32 * 32 + bg * 4;
#pragma unroll 8
            for (int k = 0; k < 32; k++) {
                float4 w4 = *(const float4*)(wp + k * 16);
                float4 h4 = *(const float4*)(hp + k * 32);
                a0.x = fmaf(w4.x, h4.x, a0.x); a0.y = fmaf(w4.x, h4.y, a0.y);
                a0.z = fmaf(w4.x, h4.z, a0.z); a0.w = fmaf(w4.x, h4.w, a0.w);
                a1.x = fmaf(w4.y, h4.x, a1.x); a1.y = fmaf(w4.y, h4.y, a1.y);
                a1.z = fmaf(w4.y, h4.z, a1.z); a1.w = fmaf(w4.y, h4.w, a1.w);
                a2.x = fmaf(w4.z, h4.x, a2.x); a2.y = fmaf(w4.z, h4.y, a2.y);
                a2.z = fmaf(w4.z, h4.z, a2.z); a2.w = fmaf(w4.z, h4.w, a2.w);
                a3.x = fmaf(w4.w, h4.x, a3.x); a3.y = fmaf(w4.w, h4.y, a3.y);
                a3.z = fmaf(w4.w, h4.z, a3.z); a3.w = fmaf(w4.w, h4.w, a3.w);
            }
            float* pp = pS + kc * 512 + (rg * 4) * 32 + bg * 4;
            *(float4*)(pp)      = a0;
            *(float4*)(pp + 32) = a1;
            *(float4*)(pp + 64) = a2;
            *(float4*)(pp + 96) = a3;
        }
        __syncthreads();
        if (tid < 128) {
            float s0 = 0.f, s1 = 0.f, s2 = 0.f, s3 = 0.f;
#pragma unroll
            for (int q = 0; q < 8; q++) {
                const float* qq = pS + q * 512 + j * 32 + b;
                s0 += qq[0]; s1 += qq[128]; s2 += qq[256]; s3 += qq[384];
            }
            float gi = s0 + pgi, gf = s1 + pgf, gg = s2 + pgg, go = s3 + pgo;
            float ii = 1.f / (1.f + expf(-gi));
            float ff = 1.f / (1.f + expf(-gf));
            float g2 = tanhf(gg);
            float oo = 1.f / (1.f + expf(-go));
            float cn = ff * cReg + ii * g2;
            float hn = oo * tanhf(cn);
            hReg = mval * hn + (1.f - mval) * hReg;
            cReg = mval * cn + (1.f - mval) * cReg;
            out[(l * 32 + b) * 512 + dir * 256 + j0 + j] = hReg;
            __stcg(&g_h[((1 - p) * 2 + dir) * 8192 + (j0 + j) * 32 + b], hReg);
        }
        __threadfence();
        GRIDBAR();
    }
}

// ---------------- CRF emission weights transpose ---------------------------
__global__ void crfwT_kernel(const float* __restrict__ cw) {
    int idx = blockIdx.x * blockDim.x + threadIdx.x;
    if (idx >= NLAB * NSS * DPAD) return;
    int d = idx & 511;
    int n = (idx >> 9) % 6;
    int k = idx / (512 * 6);
    g_crfwT[idx] = cw[k * 3072 + d * 6 + n];
}

// ---------------- emissions ------------------------------------------------
__global__ __launch_bounds__(64) void em_kernel(const float* __restrict__ crfb) {
    __shared__ __align__(16) float rowS[512];
    int bx = blockIdx.x;                 // row = l*32+b
    int l = bx >> 5, b = bx & 31;
    int tid = threadIdx.x;
    const float4* src = (const float4*)(g_out1 + bx * 512);
    float4* dst = (float4*)rowS;
    for (int i = tid; i < 128; i += 64) dst[i] = src[i];
    __syncthreads();
    if (tid < 48) {
        int k = tid / 6, n = tid % 6;
        const float* wp = g_crfwT + (k * 6 + n) * 512;
        float s = 0.f;
        for (int d = 0; d < 512; d += 4) {
            float4 w4 = *(const float4*)(wp + d);
            float4 r4 = *(const float4*)(rowS + d);
            s = fmaf(w4.x, r4.x, s); s = fmaf(w4.y, r4.y, s);
            s = fmaf(w4.z, r4.z, s); s = fmaf(w4.w, r4.w, s);
        }
        g_em[k * 24576 + b * 768 + l * 6 + n] = s + crfb[k * 6 + n];
    }
}

// ---------------- CRF forward + gold score ---------------------------------
__global__ __launch_bounds__(32) void crf_kernel(const float* __restrict__ trans,
                                                 const int* __restrict__ target,
                                                 const float* __restrict__ maskp) {
    __shared__ float trS[36];
    int k = blockIdx.x, b = threadIdx.x;
    for (int i = b; i < 36; i += 32) trS[i] = trans[k * 36 + i];
    __syncthreads();
    const float* emp = g_em + k * 24576 + b * 768;
    const int* tg = target + k * 4096 + b * 128;
    const float* mp = maskp + b * 128;
    float alpha[6];
#pragma unroll
    for (int n = 0; n < 6; n++) alpha[n] = emp[n];
    float score = emp[tg[0]] * mp[0];
    int py = tg[0];
    for (int l = 1; l < 128; l++) {
        float m = mp[l];
        const float* e = emp + l * 6;
        int y = tg[l];
        score += (e[y] + trS[py * 6 + y]) * m;
        py = y;
        float na[6];
#pragma unroll
        for (int j = 0; j < 6; j++) {
            float x0 = alpha[0] + trS[j];
            float x1 = alpha[1] + trS[6 + j];
            float x2 = alpha[2] + trS[12 + j];
            float x3 = alpha[3] + trS[18 + j];
            float x4 = alpha[4] + trS[24 + j];
            float x5 = alpha[5] + trS[30 + j];
            float mx = fmaxf(fmaxf(fmaxf(x0, x1), fmaxf(x2, x3)), fmaxf(x4, x5));
            float s = __expf(x0 - mx) + __expf(x1 - mx) + __expf(x2 - mx) +
                      __expf(x3 - mx) + __expf(x4 - mx) + __expf(x5 - mx);
            na[j] = mx + __logf(s) + e[j];
        }
#pragma unroll
        for (int j = 0; j < 6; j++) alpha[j] = m * na[j] + (1.f - m) * alpha[j];
    }
    float mx = alpha[0];
#pragma unroll
    for (int n = 1; n < 6; n++) mx = fmaxf(mx, alpha[n]);
    float s = 0.f;
#pragma unroll
    for (int n = 0; n < 6; n++) s += __expf(alpha[n] - mx);
    g_loss[k * 32 + b] = mx + __logf(s) - score;
}

// ---------------- final reduction ------------------------------------------
__global__ void reduce_kernel(float* out) {
    __shared__ float red[256];
    int tid = threadIdx.x;
    red[tid] = g_loss[tid];
    __syncthreads();
    for (int s = 128; s > 0; s >>= 1) {
        if (tid < s) red[tid] += red[tid + s];
        __syncthreads();
    }
    if (tid == 0) out[0] = red[0] * (1.f / 32.f);
}

// ---------------------------------------------------------------------------
extern "C" void kernel_launch(void* const* d_in, const int* in_sizes, int n_in,
                              void* d_out, int out_size) {
    (void)in_sizes; (void)n_in; (void)out_size;
    const int*   iv    = (const int*)d_in[0];
    const int*   ov    = (const int*)d_in[1];
    const int*   chars = (const int*)d_in[2];
    const int*   target= (const int*)d_in[3];
    const float* mask  = (const float*)d_in[4];
    const float* wtab  = (const float*)d_in[5];
    const float* otab  = (const float*)d_in[6];
    const float* ctab  = (const float*)d_in[7];
    const float* convw = (const float*)d_in[8];
    const float* convb = (const float*)d_in[9];
    const float* wih0  = (const float*)d_in[10];
    const float* whh0  = (const float*)d_in[11];
    const float* b0    = (const float*)d_in[12];
    const float* wih1  = (const float*)d_in[13];
    const float* whh1  = (const float*)d_in[14];
    const float* b1    = (const float*)d_in[15];
    const float* crfw  = (const float*)d_in[16];
    const float* crfb  = (const float*)d_in[17];
    const float* crftr = (const float*)d_in[18];

    const int SMEM_LSTM = (4096 + 8192 + 4096) * 4;  // 65536 B
    cudaFuncSetAttribute(lstm_kernel, cudaFuncAttributeMaxDynamicSharedMemorySize, SMEM_LSTM);

    embed_kernel<<<(NTOK * 300 + 255) / 256, 256>>>(iv, ov, wtab, otab);
    pad_inp_kernel<<<(NTOK * 12 + 255) / 256, 256>>>();
    pad_w_kernel<<<(2048 * DPAD + 255) / 256, 256>>>(wih0);
    chartab_kernel<<<100, 600>>>(ctab, convw);
    charconv_kernel<<<NTOK, 256>>>(chars, convb);
    crfwT_kernel<<<(NLAB * NSS * DPAD + 255) / 256, 256>>>(crfw);

    dim3 gg(16, 32);
    gemm_kernel<<<gg, 256>>>(0, (const float*)0, b0);
    lstm_kernel<<<REC_CTAS, 256, SMEM_LSTM>>>(0, whh0, mask);
    gemm_kernel<<<gg, 256>>>(1, wih1, b1);
    lstm_kernel<<<REC_CTAS, 256, SMEM_LSTM>>>(1, whh1, mask);

    em_kernel<<<NTOK, 64>>>(crfb);
    crf_kernel<<<NLAB, 32>>>(crftr, target, mask);
    reduce_kernel<<<1, 256>>>((float*)d_out);
}

// round 16
// speedup vs baseline: 2.2984x; 1.1796x over previous
#include <cuda_runtime.h>
#include <math.h>

#define NB 32
#define NL 128
#define NCH 20
#define NFILT 200
#define NHID 256
#define DPAD 512
#define NSS 6
#define NLAB 8
#define NTOK 4096

// ---------------- device scratch (no allocation allowed) -------------------
__device__ float g_inp[NTOK * DPAD];        // [l*32+b][512] (500 used, 12 pad)
__device__ float g_wih0p[2048 * DPAD];      // padded w_ih0 [2048][512]
__device__ float g_gx[NTOK * 2048];         // input projections
__device__ float g_h[2 * 2 * NHID * NB];    // [parity][dir][j][b]
__device__ float g_out0[NTOK * DPAD];
__device__ float g_out1[NTOK * DPAD];
__device__ float g_T[100 * 3 * NFILT];      // char conv table [ci][k][f]
__device__ float g_crfwT[NLAB * NSS * DPAD];
__device__ float g_em[NLAB * NB * NL * NSS];
__device__ float g_loss[NLAB * NB];
__device__ unsigned g_cnt[4];               // [layer][dir] progress counters

// ---------------- counter reset (must run before lstm each replay) ---------
__global__ void reset_kernel() {
    if (threadIdx.x < 4) g_cnt[threadIdx.x] = 0u;
}

// ---------------- word embeddings ------------------------------------------
__global__ void embed_kernel(const int* __restrict__ iv, const int* __restrict__ ov,
                             const float* __restrict__ wtab, const float* __restrict__ otab) {
    int idx = blockIdx.x * blockDim.x + threadIdx.x;
    if (idx >= NTOK * 300) return;
    int d = idx % 300, tok = idx / 300;
    int b = tok >> 7, l = tok & 127;
    float v = wtab[iv[tok] * 300 + d];
    int oi = ov[tok];
    if (oi != 0) v += otab[oi * 300 + d];
    g_inp[(l * NB + b) * DPAD + d] = v;
}

__global__ void pad_inp_kernel() {
    int idx = blockIdx.x * blockDim.x + threadIdx.x;
    if (idx >= NTOK * 12) return;
    g_inp[(idx / 12) * DPAD + 500 + (idx % 12)] = 0.f;
}

__global__ void pad_w_kernel(const float* __restrict__ w) {
    int idx = blockIdx.x * blockDim.x + threadIdx.x;
    if (idx >= 2048 * DPAD) return;
    int n = idx >> 9, k = idx & 511;
    g_wih0p[idx] = (k < 500) ? w[n * 500 + k] : 0.f;
}

// ---------------- char conv table precompute -------------------------------
// T[ci][k][f] = sum_e ctab[ci][e] * cw[f][e][k]   (T[0][*][*] = 0)
__global__ __launch_bounds__(600) void chartab_kernel(
    const float* __restrict__ ctab, const float* __restrict__ cw) {
    __shared__ float ce[50];
    int ci = blockIdx.x;
    int tid = threadIdx.x;
    if (tid < 50) ce[tid] = ctab[ci * 50 + tid];
    __syncthreads();
    int k = tid / NFILT, f = tid % NFILT;   // tid in [0,600)
    float s = 0.f;
    const float* wp = cw + f * 150 + k;
#pragma unroll 10
    for (int e = 0; e < 50; e++) s = fmaf(ce[e], wp[e * 3], s);
    g_T[ci * 600 + k * NFILT + f] = (ci == 0) ? 0.f : s;
}

// ---------------- char CNN via table + maxpool + sigmoid -------------------
__global__ __launch_bounds__(256) void charconv_kernel(
    const int* __restrict__ chars, const float* __restrict__ cb) {
    __shared__ int ci[NCH];
    int bx = blockIdx.x;                    // b*128 + l
    int b = bx >> 7, l = bx & 127;
    int tid = threadIdx.x;
    if (tid < NCH) ci[tid] = chars[bx * NCH + tid];
    __syncthreads();
    int f = tid;
    if (f < NFILT) {
        float best = -1e30f;
#pragma unroll
        for (int p = 0; p < 22; p++) {
            float s = 0.f;
#pragma unroll
            for (int k = 0; k < 3; k++) {
                int c = p + k - 2;
                if (c >= 0 && c < NCH)
                    s += g_T[ci[c] * 600 + k * NFILT + f];
            }
            best = fmaxf(best, s);
        }
        best += cb[f];
        g_inp[(l * NB + b) * DPAD + 300 + f] = 1.f / (1.f + expf(-best));
    }
}

// ---------------- input-projection GEMM (double-buffered) -------------------
// C[4096][2048] = A[4096][512] * Bw^T  (+bias)
__global__ __launch_bounds__(256, 2) void gemm_kernel(
    int layer, const float* __restrict__ Bw_ext, const float* __restrict__ bias) {
    __shared__ __align__(16) float As[2][8][128];
    __shared__ __align__(16) float Bs[2][8][128];
    const float* A  = layer ? g_out0 : g_inp;
    const float* Bw = layer ? Bw_ext : g_wih0p;
    float* C = g_gx;
    int m0 = blockIdx.y * 128, n0 = blockIdx.x * 128;
    int tid = threadIdx.x;
    int lm = tid >> 1, lk = (tid & 1) * 4;
    int ty = tid >> 4, tx = tid & 15;
    float acc[8][8];
#pragma unroll
    for (int i = 0; i < 8; i++)
#pragma unroll
        for (int j = 0; j < 8; j++) acc[i][j] = 0.f;
    const float* Ap = A + (m0 + lm) * 512 + lk;
    const float* Bp = Bw + (n0 + lm) * 512 + lk;
    float4 av = *(const float4*)Ap;
    float4 bv = *(const float4*)Bp;
    As[0][lk + 0][lm] = av.x; As[0][lk + 1][lm] = av.y;
    As[0][lk + 2][lm] = av.z; As[0][lk + 3][lm] = av.w;
    Bs[0][lk + 0][lm] = bv.x; Bs[0][lk + 1][lm] = bv.y;
    Bs[0][lk + 2][lm] = bv.z; Bs[0][lk + 3][lm] = bv.w;
    __syncthreads();
    for (int k0 = 0; k0 < 512; k0 += 8) {
        int p = (k0 >> 3) & 1;
        bool more = (k0 + 8) < 512;
        if (more) {
            av = *(const float4*)(Ap + k0 + 8);
            bv = *(const float4*)(Bp + k0 + 8);
        }
#pragma unroll
        for (int k = 0; k < 8; k++) {
            float a[8], bb[8];
            *(float4*)(a)      = *(const float4*)&As[p][k][ty * 8];
            *(float4*)(a + 4)  = *(const float4*)&As[p][k][ty * 8 + 4];
            *(float4*)(bb)     = *(const float4*)&Bs[p][k][tx * 8];
            *(float4*)(bb + 4) = *(const float4*)&Bs[p][k][tx * 8 + 4];
#pragma unroll
            for (int i = 0; i < 8; i++)
#pragma unroll
                for (int j = 0; j < 8; j++) acc[i][j] = fmaf(a[i], bb[j], acc[i][j]);
        }
        if (more) {
            int q = p ^ 1;
            As[q][lk + 0][lm] = av.x; As[q][lk + 1][lm] = av.y;
            As[q][lk + 2][lm] = av.z; As[q][lk + 3][lm] = av.w;
            Bs[q][lk + 0][lm] = bv.x; Bs[q][lk + 1][lm] = bv.y;
            Bs[q][lk + 2][lm] = bv.z; Bs[q][lk + 3][lm] = bv.w;
            __syncthreads();
        }
    }
    float bb2[8];
#pragma unroll
    for (int j = 0; j < 8; j++) bb2[j] = bias[n0 + tx * 8 + j];
#pragma unroll
    for (int i = 0; i < 8; i++) {
        float* Cp = C + (m0 + ty * 8 + i) * 2048 + n0 + tx * 8;
        float4 v0 = make_float4(acc[i][0] + bb2[0], acc[i][1] + bb2[1],
                                acc[i][2] + bb2[2], acc[i][3] + bb2[3]);
        float4 v1 = make_float4(acc[i][4] + bb2[4], acc[i][5] + bb2[5],
                                acc[i][6] + bb2[6], acc[i][7] + bb2[7]);
        *(float4*)Cp = v0;
        *(float4*)(Cp + 4) = v1;
    }
}

// ---------------- persistent BiLSTM layer (per-dir release counters) --------
// 128 CTAs: dir (2) x slice (64 of 4 hidden units = 16 gate rows).
// smem: wS [256k][16r] 16KB | hS [256k][32b] 32KB | pS [8kc][512] 16KB
// Sync: monotone counter per (layer,dir). Producer: syncthreads -> tid0
// red.release.gpu.add(1). Consumer: tid0 ld.acquire.gpu poll -> syncthreads.
// Double-buffered h + monotone counter gives the 2-step WAR separation.
__device__ __forceinline__ void cnt_release(unsigned* p) {
    asm volatile("red.release.gpu.global.add.u32 [%0], %1;" :: "l"(p), "r"(1u) : "memory");
}
__device__ __forceinline__ unsigned cnt_acquire(const unsigned* p) {
    unsigned v;
    asm volatile("ld.acquire.gpu.global.u32 %0, [%1];" : "=r"(v) : "l"(p) : "memory");
    return v;
}

__global__ __launch_bounds__(256) void lstm_kernel(
    int layer, const float* __restrict__ whh, const float* __restrict__ maskp) {
    extern __shared__ float sm[];
    float* wS = sm;
    float* hS = sm + 4096;
    float* pS = sm + 4096 + 8192;
    float* out = layer ? g_out1 : g_out0;
    int tid = threadIdx.x;
    int dir = blockIdx.x >> 6;
    int j0 = (blockIdx.x & 63) * 4;
    unsigned* cnt = &g_cnt[layer * 2 + dir];
    // load w_hh slice (16 gate rows) into k-major smem
    for (int idx = tid; idx < 4096; idx += 256) {
        int r = idx >> 8, k = idx & 255;                       // r=gate*4+jl
        int row = (r >> 2) * 256 + j0 + (r & 3);
        wS[k * 16 + r] = __ldg(&whh[dir * 262144 + row * 256 + k]);
    }
    int kc = tid >> 5, lane = tid & 31;
    int rg = lane >> 3, bg = lane & 7;
    int j = tid >> 5, b = tid & 31;       // elementwise mapping (tid<128)
    float cReg = 0.f, hReg = 0.f;
    if (tid < 128)
        __stcg(&g_h[dir * 8192 + (j0 + j) * 32 + b], 0.f);     // parity-0 init
    __syncthreads();
    if (tid == 0) cnt_release(cnt);                            // init counts as step -1
    for (int t = 0; t < 128; t++) {
        int p = t & 1;
        int l = dir ? (127 - t) : t;
        float pgi = 0.f, pgf = 0.f, pgg = 0.f, pgo = 0.f, mval = 0.f;
        if (tid < 128) {   // prefetch gx + mask (independent of h)
            const float* gxp = g_gx + (l * 32 + b) * 2048 + dir * 1024 + j0 + j;
            pgi = gxp[0]; pgf = gxp[256]; pgg = gxp[512]; pgo = gxp[768];
            mval = maskp[b * 128 + l];
        }
        // wait until all 64 CTAs of this dir published h for step t-1
        if (tid == 0) {
            unsigned target = 64u * (unsigned)(t + 1);
            while (cnt_acquire(cnt) < target) __nanosleep(32);
        }
        __syncthreads();
        // stage h_prev (L2-coherent path)
        {
            const float4* hsrc = (const float4*)(g_h + (p * 2 + dir) * 8192);
            float4* hdst = (float4*)hS;
#pragma unroll
            for (int i = 0; i < 8; i++)
                hdst[tid + i * 256] = __ldcg(hsrc + tid + i * 256);
        }
        __syncthreads();
        // 16 rows x 32 batch x K=256, 8-way K-split, 4x4 outer product
        {
            float4 a0 = {0,0,0,0}, a1 = {0,0,0,0}, a2 = {0,0,0,0}, a3 = {0,0,0,0};
            const float* wp = wS + kc * 32 * 16 + rg * 4;
            const float* hp = hS + kc * 32 * 32 + bg * 4;
#pragma unroll 8
            for (int k = 0; k < 32; k++) {
                float4 w4 = *(const float4*)(wp + k * 16);
                float4 h4 = *(const float4*)(hp + k * 32);
                a0.x = fmaf(w4.x, h4.x, a0.x); a0.y = fmaf(w4.x, h4.y, a0.y);
                a0.z = fmaf(w4.x, h4.z, a0.z); a0.w = fmaf(w4.x, h4.w, a0.w);
                a1.x = fmaf(w4.y, h4.x, a1.x); a1.y = fmaf(w4.y, h4.y, a1.y);
                a1.z = fmaf(w4.y, h4.z, a1.z); a1.w = fmaf(w4.y, h4.w, a1.w);
                a2.x = fmaf(w4.z, h4.x, a2.x); a2.y = fmaf(w4.z, h4.y, a2.y);
                a2.z = fmaf(w4.z, h4.z, a2.z); a2.w = fmaf(w4.z, h4.w, a2.w);
                a3.x = fmaf(w4.w, h4.x, a3.x); a3.y = fmaf(w4.w, h4.y, a3.y);
                a3.z = fmaf(w4.w, h4.z, a3.z); a3.w = fmaf(w4.w, h4.w, a3.w);
            }
            float* pp = pS + kc * 512 + (rg * 4) * 32 + bg * 4;
            *(float4*)(pp)      = a0;
            *(float4*)(pp + 32) = a1;
            *(float4*)(pp + 64) = a2;
            *(float4*)(pp + 96) = a3;
        }
        __syncthreads();
        if (tid < 128) {
            float s0 = 0.f, s1 = 0.f, s2 = 0.f, s3 = 0.f;
#pragma unroll
            for (int q = 0; q < 8; q++) {
                const float* qq = pS + q * 512 + j * 32 + b;
                s0 += qq[0]; s1 += qq[128]; s2 += qq[256]; s3 += qq[384];
            }
            float gi = s0 + pgi, gf = s1 + pgf, gg = s2 + pgg, go = s3 + pgo;
            float ii = 1.f / (1.f + expf(-gi));
            float ff = 1.f / (1.f + expf(-gf));
            float g2 = tanhf(gg);
            float oo = 1.f / (1.f + expf(-go));
            float cn = ff * cReg + ii * g2;
            float hn = oo * tanhf(cn);
            hReg = mval * hn + (1.f - mval) * hReg;
            cReg = mval * cn + (1.f - mval) * cReg;
            out[(l * 32 + b) * 512 + dir * 256 + j0 + j] = hReg;
            __stcg(&g_h[((1 - p) * 2 + dir) * 8192 + (j0 + j) * 32 + b], hReg);
        }
        __syncthreads();               // all h writes of this CTA done
        if (tid == 0) cnt_release(cnt);    // publish step t
    }
}

// ---------------- CRF emission weights transpose ---------------------------
__global__ void crfwT_kernel(const float* __restrict__ cw) {
    int idx = blockIdx.x * blockDim.x + threadIdx.x;
    if (idx >= NLAB * NSS * DPAD) return;
    int d = idx & 511;
    int n = (idx >> 9) % 6;
    int k = idx / (512 * 6);
    g_crfwT[idx] = cw[k * 3072 + d * 6 + n];
}

// ---------------- emissions ------------------------------------------------
__global__ __launch_bounds__(64) void em_kernel(const float* __restrict__ crfb) {
    __shared__ __align__(16) float rowS[512];
    int bx = blockIdx.x;                 // row = l*32+b
    int l = bx >> 5, b = bx & 31;
    int tid = threadIdx.x;
    const float4* src = (const float4*)(g_out1 + bx * 512);
    float4* dst = (float4*)rowS;
    for (int i = tid; i < 128; i += 64) dst[i] = src[i];
    __syncthreads();
    if (tid < 48) {
        int k = tid / 6, n = tid % 6;
        const float* wp = g_crfwT + (k * 6 + n) * 512;
        float s = 0.f;
        for (int d = 0; d < 512; d += 4) {
            float4 w4 = *(const float4*)(wp + d);
            float4 r4 = *(const float4*)(rowS + d);
            s = fmaf(w4.x, r4.x, s); s = fmaf(w4.y, r4.y, s);
            s = fmaf(w4.z, r4.z, s); s = fmaf(w4.w, r4.w, s);
        }
        g_em[k * 24576 + b * 768 + l * 6 + n] = s + crfb[k * 6 + n];
    }
}

// ---------------- CRF forward + gold score ---------------------------------
__global__ __launch_bounds__(32) void crf_kernel(const float* __restrict__ trans,
                                                 const int* __restrict__ target,
                                                 const float* __restrict__ maskp) {
    __shared__ float trS[36];
    int k = blockIdx.x, b = threadIdx.x;
    for (int i = b; i < 36; i += 32) trS[i] = trans[k * 36 + i];
    __syncthreads();
    const float* emp = g_em + k * 24576 + b * 768;
    const int* tg = target + k * 4096 + b * 128;
    const float* mp = maskp + b * 128;
    float alpha[6];
#pragma unroll
    for (int n = 0; n < 6; n++) alpha[n] = emp[n];
    float score = emp[tg[0]] * mp[0];
    int py = tg[0];
    for (int l = 1; l < 128; l++) {
        float m = mp[l];
        const float* e = emp + l * 6;
        int y = tg[l];
        score += (e[y] + trS[py * 6 + y]) * m;
        py = y;
        float na[6];
#pragma unroll
        for (int j = 0; j < 6; j++) {
            float x0 = alpha[0] + trS[j];
            float x1 = alpha[1] + trS[6 + j];
            float x2 = alpha[2] + trS[12 + j];
            float x3 = alpha[3] + trS[18 + j];
            float x4 = alpha[4] + trS[24 + j];
            float x5 = alpha[5] + trS[30 + j];
            float mx = fmaxf(fmaxf(fmaxf(x0, x1), fmaxf(x2, x3)), fmaxf(x4, x5));
            float s = __expf(x0 - mx) + __expf(x1 - mx) + __expf(x2 - mx) +
                      __expf(x3 - mx) + __expf(x4 - mx) + __expf(x5 - mx);
            na[j] = mx + __logf(s) + e[j];
        }
#pragma unroll
        for (int j = 0; j < 6; j++) alpha[j] = m * na[j] + (1.f - m) * alpha[j];
    }
    float mx = alpha[0];
#pragma unroll
    for (int n = 1; n < 6; n++) mx = fmaxf(mx, alpha[n]);
    float s = 0.f;
#pragma unroll
    for (int n = 0; n < 6; n++) s += __expf(alpha[n] - mx);
    g_loss[k * 32 + b] = mx + __logf(s) - score;
}

// ---------------- final reduction ------------------------------------------
__global__ void reduce_kernel(float* out) {
    __shared__ float red[256];
    int tid = threadIdx.x;
    red[tid] = g_loss[tid];
    __syncthreads();
    for (int s = 128; s > 0; s >>= 1) {
        if (tid < s) red[tid] += red[tid + s];
        __syncthreads();
    }
    if (tid == 0) out[0] = red[0] * (1.f / 32.f);
}

// ---------------------------------------------------------------------------
extern "C" void kernel_launch(void* const* d_in, const int* in_sizes, int n_in,
                              void* d_out, int out_size) {
    (void)in_sizes; (void)n_in; (void)out_size;
    const int*   iv    = (const int*)d_in[0];
    const int*   ov    = (const int*)d_in[1];
    const int*   chars = (const int*)d_in[2];
    const int*   target= (const int*)d_in[3];
    const float* mask  = (const float*)d_in[4];
    const float* wtab  = (const float*)d_in[5];
    const float* otab  = (const float*)d_in[6];
    const float* ctab  = (const float*)d_in[7];
    const float* convw = (const float*)d_in[8];
    const float* convb = (const float*)d_in[9];
    const float* wih0  = (const float*)d_in[10];
    const float* whh0  = (const float*)d_in[11];
    const float* b0    = (const float*)d_in[12];
    const float* wih1  = (const float*)d_in[13];
    const float* whh1  = (const float*)d_in[14];
    const float* b1    = (const float*)d_in[15];
    const float* crfw  = (const float*)d_in[16];
    const float* crfb  = (const float*)d_in[17];
    const float* crftr = (const float*)d_in[18];

    const int SMEM_LSTM = (4096 + 8192 + 4096) * 4;  // 65536 B
    cudaFuncSetAttribute(lstm_kernel, cudaFuncAttributeMaxDynamicSharedMemorySize, SMEM_LSTM);

    reset_kernel<<<1, 32>>>();
    embed_kernel<<<(NTOK * 300 + 255) / 256, 256>>>(iv, ov, wtab, otab);
    pad_inp_kernel<<<(NTOK * 12 + 255) / 256, 256>>>();
    pad_w_kernel<<<(2048 * DPAD + 255) / 256, 256>>>(wih0);
    chartab_kernel<<<100, 600>>>(ctab, convw);
    charconv_kernel<<<NTOK, 256>>>(chars, convb);
    crfwT_kernel<<<(NLAB * NSS * DPAD + 255) / 256, 256>>>(crfw);

    dim3 gg(16, 32);
    gemm_kernel<<<gg, 256>>>(0, (const float*)0, b0);
    lstm_kernel<<<128, 256, SMEM_LSTM>>>(0, whh0, mask);
    gemm_kernel<<<gg, 256>>>(1, wih1, b1);
    lstm_kernel<<<128, 256, SMEM_LSTM>>>(1, whh1, mask);

    em_kernel<<<NTOK, 64>>>(crfb);
    crf_kernel<<<NLAB, 32>>>(crftr, target, mask);
    reduce_kernel<<<1, 256>>>((float*)d_out);
}

// round 17
// speedup vs baseline: 2.8340x; 1.2330x over previous
#include <cuda_runtime.h>
#include <math.h>

#define NB 32
#define NL 128
#define NCH 20
#define NFILT 200
#define NHID 256
#define DPAD 512
#define NSS 6
#define NLAB 8
#define NTOK 4096

// ---------------- device scratch (no allocation allowed) -------------------
__device__ float g_inp[NTOK * DPAD];        // [l*32+b][512] (500 used, 12 pad)
__device__ float g_wih0p[2048 * DPAD];      // padded w_ih0 [2048][512]
__device__ float g_gx[NTOK * 2048];         // input projections
__device__ float g_h[2 * 2 * NHID * NB];    // [parity][dir][j][b]
__device__ float g_out0[NTOK * DPAD];
__device__ float g_out1[NTOK * DPAD];
__device__ float g_T[100 * 3 * NFILT];      // char conv table [ci][k][f]
__device__ float g_crfwT[NLAB * NSS * DPAD];
__device__ float g_em[NLAB * NB * NL * NSS];
__device__ float g_loss[NLAB * NB];
__device__ unsigned g_cnt[4];               // [layer][dir] progress counters

// ---------------- counter reset (must run before lstm each replay) ---------
__global__ void reset_kernel() {
    if (threadIdx.x < 4) g_cnt[threadIdx.x] = 0u;
}

// ---------------- word embeddings ------------------------------------------
__global__ void embed_kernel(const int* __restrict__ iv, const int* __restrict__ ov,
                             const float* __restrict__ wtab, const float* __restrict__ otab) {
    int idx = blockIdx.x * blockDim.x + threadIdx.x;
    if (idx >= NTOK * 300) return;
    int d = idx % 300, tok = idx / 300;
    int b = tok >> 7, l = tok & 127;
    float v = wtab[iv[tok] * 300 + d];
    int oi = ov[tok];
    if (oi != 0) v += otab[oi * 300 + d];
    g_inp[(l * NB + b) * DPAD + d] = v;
}

__global__ void pad_inp_kernel() {
    int idx = blockIdx.x * blockDim.x + threadIdx.x;
    if (idx >= NTOK * 12) return;
    g_inp[(idx / 12) * DPAD + 500 + (idx % 12)] = 0.f;
}

__global__ void pad_w_kernel(const float* __restrict__ w) {
    int idx = blockIdx.x * blockDim.x + threadIdx.x;
    if (idx >= 2048 * DPAD) return;
    int n = idx >> 9, k = idx & 511;
    g_wih0p[idx] = (k < 500) ? w[n * 500 + k] : 0.f;
}

// ---------------- char conv table precompute -------------------------------
__global__ __launch_bounds__(600) void chartab_kernel(
    const float* __restrict__ ctab, const float* __restrict__ cw) {
    __shared__ float ce[50];
    int ci = blockIdx.x;
    int tid = threadIdx.x;
    if (tid < 50) ce[tid] = ctab[ci * 50 + tid];
    __syncthreads();
    int k = tid / NFILT, f = tid % NFILT;
    float s = 0.f;
    const float* wp = cw + f * 150 + k;
#pragma unroll 10
    for (int e = 0; e < 50; e++) s = fmaf(ce[e], wp[e * 3], s);
    g_T[ci * 600 + k * NFILT + f] = (ci == 0) ? 0.f : s;
}

// ---------------- char CNN via table + maxpool + sigmoid -------------------
__global__ __launch_bounds__(256) void charconv_kernel(
    const int* __restrict__ chars, const float* __restrict__ cb) {
    __shared__ int ci[NCH];
    int bx = blockIdx.x;                    // b*128 + l
    int b = bx >> 7, l = bx & 127;
    int tid = threadIdx.x;
    if (tid < NCH) ci[tid] = chars[bx * NCH + tid];
    __syncthreads();
    int f = tid;
    if (f < NFILT) {
        float best = -1e30f;
#pragma unroll
        for (int p = 0; p < 22; p++) {
            float s = 0.f;
#pragma unroll
            for (int k = 0; k < 3; k++) {
                int c = p + k - 2;
                if (c >= 0 && c < NCH)
                    s += g_T[ci[c] * 600 + k * NFILT + f];
            }
            best = fmaxf(best, s);
        }
        best += cb[f];
        g_inp[(l * NB + b) * DPAD + 300 + f] = 1.f / (1.f + expf(-best));
    }
}

// ---------------- TF32 tensor-core GEMM ------------------------------------
// C[4096][2048] = A[4096][512] * Bw[2048][512]^T (+bias)
// CTA 128x128, 8 warps of 32x64. K staged 16 at a time, double buffered.
// smem row stride 20 floats: STS.128-aligned and conflict-free fragment LDS.
__device__ __forceinline__ unsigned f2tf32(float x) {
    unsigned u;
    asm("cvt.rna.tf32.f32 %0, %1;" : "=r"(u) : "f"(x));
    return u;
}
__device__ __forceinline__ void mma_tf32(
    float& c0, float& c1, float& c2, float& c3,
    unsigned a0, unsigned a1, unsigned a2, unsigned a3,
    unsigned b0, unsigned b1) {
    asm volatile(
        "mma.sync.aligned.m16n8k8.row.col.f32.tf32.tf32.f32 "
        "{%0,%1,%2,%3}, {%4,%5,%6,%7}, {%8,%9}, {%0,%1,%2,%3};"
        : "+f"(c0), "+f"(c1), "+f"(c2), "+f"(c3)
        : "r"(a0), "r"(a1), "r"(a2), "r"(a3), "r"(b0), "r"(b1));
}

#define SROW 20

__global__ __launch_bounds__(256) void gemm_kernel(
    int layer, const float* __restrict__ Bw_ext, const float* __restrict__ bias) {
    __shared__ __align__(16) unsigned As[2][128 * SROW];
    __shared__ __align__(16) unsigned Bs[2][128 * SROW];
    const float* A  = layer ? g_out0 : g_inp;
    const float* Bw = layer ? Bw_ext : g_wih0p;
    float* C = g_gx;
    int m0 = blockIdx.y * 128, n0 = blockIdx.x * 128;
    int tid = threadIdx.x;
    int warp = tid >> 5, lane = tid & 31;
    int g = lane >> 2, t4 = lane & 3;
    int wm = (warp >> 1) * 32, wn = (warp & 1) * 64;
    int srow = tid >> 1;                 // staging row 0..127
    int soff = (tid & 1) * 8;            // 8-float half of the 16-float k-slab
    const float* aG = A  + (m0 + srow) * 512 + soff;
    const float* bG = Bw + (n0 + srow) * 512 + soff;
    unsigned* aS = &As[0][0];
    unsigned* bS = &Bs[0][0];
    float acc[2][8][4];
#pragma unroll
    for (int mi = 0; mi < 2; mi++)
#pragma unroll
        for (int nj = 0; nj < 8; nj++)
#pragma unroll
            for (int q = 0; q < 4; q++) acc[mi][nj][q] = 0.f;

    float4 apf0, apf1, bpf0, bpf1;
    apf0 = *(const float4*)(aG);     apf1 = *(const float4*)(aG + 4);
    bpf0 = *(const float4*)(bG);     bpf1 = *(const float4*)(bG + 4);
    {
        unsigned* ad = aS + srow * SROW + soff;
        ad[0] = f2tf32(apf0.x); ad[1] = f2tf32(apf0.y);
        ad[2] = f2tf32(apf0.z); ad[3] = f2tf32(apf0.w);
        ad[4] = f2tf32(apf1.x); ad[5] = f2tf32(apf1.y);
        ad[6] = f2tf32(apf1.z); ad[7] = f2tf32(apf1.w);
        unsigned* bd = bS + srow * SROW + soff;
        bd[0] = f2tf32(bpf0.x); bd[1] = f2tf32(bpf0.y);
        bd[2] = f2tf32(bpf0.z); bd[3] = f2tf32(bpf0.w);
        bd[4] = f2tf32(bpf1.x); bd[5] = f2tf32(bpf1.y);
        bd[6] = f2tf32(bpf1.z); bd[7] = f2tf32(bpf1.w);
    }
    __syncthreads();

    for (int ks = 0; ks < 32; ks++) {
        int buf = ks & 1;
        bool more = (ks + 1) < 32;
        if (more) {
            int k0 = (ks + 1) * 16;
            apf0 = *(const float4*)(aG + k0);  apf1 = *(const float4*)(aG + k0 + 4);
            bpf0 = *(const float4*)(bG + k0);  bpf1 = *(const float4*)(bG + k0 + 4);
        }
        const unsigned* Au = &As[buf][0];
        const unsigned* Bu = &Bs[buf][0];
#pragma unroll
        for (int kk = 0; kk < 16; kk += 8) {
            unsigned af[2][4];
#pragma unroll
            for (int mi = 0; mi < 2; mi++) {
                const unsigned* ap = Au + (wm + mi * 16 + g) * SROW + kk + t4;
                af[mi][0] = ap[0];
                af[mi][1] = ap[8 * SROW];
                af[mi][2] = ap[4];
                af[mi][3] = ap[8 * SROW + 4];
            }
#pragma unroll
            for (int nj = 0; nj < 8; nj++) {
                const unsigned* bp = Bu + (wn + nj * 8 + g) * SROW + kk + t4;
                unsigned b0 = bp[0], b1 = bp[4];
                mma_tf32(acc[0][nj][0], acc[0][nj][1], acc[0][nj][2], acc[0][nj][3],
                         af[0][0], af[0][1], af[0][2], af[0][3], b0, b1);
                mma_tf32(acc[1][nj][0], acc[1][nj][1], acc[1][nj][2], acc[1][nj][3],
                         af[1][0], af[1][1], af[1][2], af[1][3], b0, b1);
            }
        }
        if (more) {
            int nb = buf ^ 1;
            unsigned* ad = &As[nb][0] + srow * SROW + soff;
            ad[0] = f2tf32(apf0.x); ad[1] = f2tf32(apf0.y);
            ad[2] = f2tf32(apf0.z); ad[3] = f2tf32(apf0.w);
            ad[4] = f2tf32(apf1.x); ad[5] = f2tf32(apf1.y);
            ad[6] = f2tf32(apf1.z); ad[7] = f2tf32(apf1.w);
            unsigned* bd = &Bs[nb][0] + srow * SROW + soff;
            bd[0] = f2tf32(bpf0.x); bd[1] = f2tf32(bpf0.y);
            bd[2] = f2tf32(bpf0.z); bd[3] = f2tf32(bpf0.w);
            bd[4] = f2tf32(bpf1.x); bd[5] = f2tf32(bpf1.y);
            bd[6] = f2tf32(bpf1.z); bd[7] = f2tf32(bpf1.w);
            __syncthreads();
        }
    }
    // epilogue: c0/c1 at (r, 2*t4), c2/c3 at (r+8, 2*t4)
#pragma unroll
    for (int mi = 0; mi < 2; mi++) {
        int r0 = m0 + wm + mi * 16 + g;
#pragma unroll
        for (int nj = 0; nj < 8; nj++) {
            int col = n0 + wn + nj * 8 + 2 * t4;
            float b0 = bias[col], b1 = bias[col + 1];
            float2 v0 = make_float2(acc[mi][nj][0] + b0, acc[mi][nj][1] + b1);
            float2 v1 = make_float2(acc[mi][nj][2] + b0, acc[mi][nj][3] + b1);
            *(float2*)(C + r0 * 2048 + col) = v0;
            *(float2*)(C + (r0 + 8) * 2048 + col) = v1;
        }
    }
}

// ---------------- persistent BiLSTM layer (per-dir release counters) --------
__device__ __forceinline__ void cnt_release(unsigned* p) {
    asm volatile("red.release.gpu.global.add.u32 [%0], %1;" :: "l"(p), "r"(1u) : "memory");
}
__device__ __forceinline__ unsigned cnt_acquire(const unsigned* p) {
    unsigned v;
    asm volatile("ld.acquire.gpu.global.u32 %0, [%1];" : "=r"(v) : "l"(p) : "memory");
    return v;
}

__global__ __launch_bounds__(256) void lstm_kernel(
    int layer, const float* __restrict__ whh, const float* __restrict__ maskp) {
    extern __shared__ float sm[];
    float* wS = sm;
    float* hS = sm + 4096;
    float* pS = sm + 4096 + 8192;
    float* out = layer ? g_out1 : g_out0;
    int tid = threadIdx.x;
    int dir = blockIdx.x >> 6;
    int j0 = (blockIdx.x & 63) * 4;
    unsigned* cnt = &g_cnt[layer * 2 + dir];
    for (int idx = tid; idx < 4096; idx += 256) {
        int r = idx >> 8, k = idx & 255;
        int row = (r >> 2) * 256 + j0 + (r & 3);
        wS[k * 16 + r] = __ldg(&whh[dir * 262144 + row * 256 + k]);
    }
    int kc = tid >> 5, lane = tid & 31;
    int rg = lane >> 3, bg = lane & 7;
    int j = tid >> 5, b = tid & 31;
    float cReg = 0.f, hReg = 0.f;
    if (tid < 128)
        __stcg(&g_h[dir * 8192 + (j0 + j) * 32 + b], 0.f);
    __syncthreads();
    if (tid == 0) cnt_release(cnt);
    for (int t = 0; t < 128; t++) {
        int p = t & 1;
        int l = dir ? (127 - t) : t;
        float pgi = 0.f, pgf = 0.f, pgg = 0.f, pgo = 0.f, mval = 0.f;
        if (tid < 128) {
            const float* gxp = g_gx + (l * 32 + b) * 2048 + dir * 1024 + j0 + j;
            pgi = gxp[0]; pgf = gxp[256]; pgg = gxp[512]; pgo = gxp[768];
            mval = maskp[b * 128 + l];
        }
        if (tid == 0) {
            unsigned target = 64u * (unsigned)(t + 1);
            while (cnt_acquire(cnt) < target) __nanosleep(32);
        }
        __syncthreads();
        {
            const float4* hsrc = (const float4*)(g_h + (p * 2 + dir) * 8192);
            float4* hdst = (float4*)hS;
#pragma unroll
            for (int i = 0; i < 8; i++)
                hdst[tid + i * 256] = __ldcg(hsrc + tid + i * 256);
        }
        __syncthreads();
        {
            float4 a0 = {0,0,0,0}, a1 = {0,0,0,0}, a2 = {0,0,0,0}, a3 = {0,0,0,0};
            const float* wp = wS + kc * 32 * 16 + rg * 4;
            const float* hp = hS + kc * 32 * 32 + bg * 4;
#pragma unroll 8
            for (int k = 0; k < 32; k++) {
                float4 w4 = *(const float4*)(wp + k * 16);
                float4 h4 = *(const float4*)(hp + k * 32);
                a0.x = fmaf(w4.x, h4.x, a0.x); a0.y = fmaf(w4.x, h4.y, a0.y);
                a0.z = fmaf(w4.x, h4.z, a0.z); a0.w = fmaf(w4.x, h4.w, a0.w);
                a1.x = fmaf(w4.y, h4.x, a1.x); a1.y = fmaf(w4.y, h4.y, a1.y);
                a1.z = fmaf(w4.y, h4.z, a1.z); a1.w = fmaf(w4.y, h4.w, a1.w);
                a2.x = fmaf(w4.z, h4.x, a2.x); a2.y = fmaf(w4.z, h4.y, a2.y);
                a2.z = fmaf(w4.z, h4.z, a2.z); a2.w = fmaf(w4.z, h4.w, a2.w);
                a3.x = fmaf(w4.w, h4.x, a3.x); a3.y = fmaf(w4.w, h4.y, a3.y);
                a3.z = fmaf(w4.w, h4.z, a3.z); a3.w = fmaf(w4.w, h4.w, a3.w);
            }
            float* pp = pS + kc * 512 + (rg * 4) * 32 + bg * 4;
            *(float4*)(pp)      = a0;
            *(float4*)(pp + 32) = a1;
            *(float4*)(pp + 64) = a2;
            *(float4*)(pp + 96) = a3;
        }
        __syncthreads();
        if (tid < 128) {
            float s0 = 0.f, s1 = 0.f, s2 = 0.f, s3 = 0.f;
#pragma unroll
            for (int q = 0; q < 8; q++) {
                const float* qq = pS + q * 512 + j * 32 + b;
                s0 += qq[0]; s1 += qq[128]; s2 += qq[256]; s3 += qq[384];
            }
            float gi = s0 + pgi, gf = s1 + pgf, gg = s2 + pgg, go = s3 + pgo;
            float ii = 1.f / (1.f + expf(-gi));
            float ff = 1.f / (1.f + expf(-gf));
            float g2 = tanhf(gg);
            float oo = 1.f / (1.f + expf(-go));
            float cn = ff * cReg + ii * g2;
            float hn = oo * tanhf(cn);
            hReg = mval * hn + (1.f - mval) * hReg;
            cReg = mval * cn + (1.f - mval) * cReg;
            out[(l * 32 + b) * 512 + dir * 256 + j0 + j] = hReg;
            __stcg(&g_h[((1 - p) * 2 + dir) * 8192 + (j0 + j) * 32 + b], hReg);
        }
        __syncthreads();
        if (tid == 0) cnt_release(cnt);
    }
}

// ---------------- CRF emission weights transpose ---------------------------
__global__ void crfwT_kernel(const float* __restrict__ cw) {
    int idx = blockIdx.x * blockDim.x + threadIdx.x;
    if (idx >= NLAB * NSS * DPAD) return;
    int d = idx & 511;
    int n = (idx >> 9) % 6;
    int k = idx / (512 * 6);
    g_crfwT[idx] = cw[k * 3072 + d * 6 + n];
}

// ---------------- emissions ------------------------------------------------
__global__ __launch_bounds__(64) void em_kernel(const float* __restrict__ crfb) {
    __shared__ __align__(16) float rowS[512];
    int bx = blockIdx.x;                 // row = l*32+b
    int l = bx >> 5, b = bx & 31;
    int tid = threadIdx.x;
    const float4* src = (const float4*)(g_out1 + bx * 512);
    float4* dst = (float4*)rowS;
    for (int i = tid; i < 128; i += 64) dst[i] = src[i];
    __syncthreads();
    if (tid < 48) {
        int k = tid / 6, n = tid % 6;
        const float* wp = g_crfwT + (k * 6 + n) * 512;
        float s = 0.f;
        for (int d = 0; d < 512; d += 4) {
            float4 w4 = *(const float4*)(wp + d);
            float4 r4 = *(const float4*)(rowS + d);
            s = fmaf(w4.x, r4.x, s); s = fmaf(w4.y, r4.y, s);
            s = fmaf(w4.z, r4.z, s); s = fmaf(w4.w, r4.w, s);
        }
        g_em[k * 24576 + b * 768 + l * 6 + n] = s + crfb[k * 6 + n];
    }
}

// ---------------- CRF forward + gold score ---------------------------------
__global__ __launch_bounds__(32) void crf_kernel(const float* __restrict__ trans,
                                                 const int* __restrict__ target,
                                                 const float* __restrict__ maskp) {
    __shared__ float trS[36];
    int k = blockIdx.x, b = threadIdx.x;
    for (int i = b; i < 36; i += 32) trS[i] = trans[k * 36 + i];
    __syncthreads();
    const float* emp = g_em + k * 24576 + b * 768;
    const int* tg = target + k * 4096 + b * 128;
    const float* mp = maskp + b * 128;
    float alpha[6];
#pragma unroll
    for (int n = 0; n < 6; n++) alpha[n] = emp[n];
    float score = emp[tg[0]] * mp[0];
    int py = tg[0];
    for (int l = 1; l < 128; l++) {
        float m = mp[l];
        const float* e = emp + l * 6;
        int y = tg[l];
        score += (e[y] + trS[py * 6 + y]) * m;
        py = y;
        float na[6];
#pragma unroll
        for (int j = 0; j < 6; j++) {
            float x0 = alpha[0] + trS[j];
            float x1 = alpha[1] + trS[6 + j];
            float x2 = alpha[2] + trS[12 + j];
            float x3 = alpha[3] + trS[18 + j];
            float x4 = alpha[4] + trS[24 + j];
            float x5 = alpha[5] + trS[30 + j];
            float mx = fmaxf(fmaxf(fmaxf(x0, x1), fmaxf(x2, x3)), fmaxf(x4, x5));
            float s = __expf(x0 - mx) + __expf(x1 - mx) + __expf(x2 - mx) +
                      __expf(x3 - mx) + __expf(x4 - mx) + __expf(x5 - mx);
            na[j] = mx + __logf(s) + e[j];
        }
#pragma unroll
        for (int j = 0; j < 6; j++) alpha[j] = m * na[j] + (1.f - m) * alpha[j];
    }
    float mx = alpha[0];
#pragma unroll
    for (int n = 1; n < 6; n++) mx = fmaxf(mx, alpha[n]);
    float s = 0.f;
#pragma unroll
    for (int n = 0; n < 6; n++) s += __expf(alpha[n] - mx);
    g_loss[k * 32 + b] = mx + __logf(s) - score;
}

// ---------------- final reduction ------------------------------------------
__global__ void reduce_kernel(float* out) {
    __shared__ float red[256];
    int tid = threadIdx.x;
    red[tid] = g_loss[tid];
    __syncthreads();
    for (int s = 128; s > 0; s >>= 1) {
        if (tid < s) red[tid] += red[tid + s];
        __syncthreads();
    }
    if (tid == 0) out[0] = red[0] * (1.f / 32.f);
}

// ---------------------------------------------------------------------------
extern "C" void kernel_launch(void* const* d_in, const int* in_sizes, int n_in,
                              void* d_out, int out_size) {
    (void)in_sizes; (void)n_in; (void)out_size;
    const int*   iv    = (const int*)d_in[0];
    const int*   ov    = (const int*)d_in[1];
    const int*   chars = (const int*)d_in[2];
    const int*   target= (const int*)d_in[3];
    const float* mask  = (const float*)d_in[4];
    const float* wtab  = (const float*)d_in[5];
    const float* otab  = (const float*)d_in[6];
    const float* ctab  = (const float*)d_in[7];
    const float* convw = (const float*)d_in[8];
    const float* convb = (const float*)d_in[9];
    const float* wih0  = (const float*)d_in[10];
    const float* whh0  = (const float*)d_in[11];
    const float* b0    = (const float*)d_in[12];
    const float* wih1  = (const float*)d_in[13];
    const float* whh1  = (const float*)d_in[14];
    const float* b1    = (const float*)d_in[15];
    const float* crfw  = (const float*)d_in[16];
    const float* crfb  = (const float*)d_in[17];
    const float* crftr = (const float*)d_in[18];

    const int SMEM_LSTM = (4096 + 8192 + 4096) * 4;  // 65536 B
    cudaFuncSetAttribute(lstm_kernel, cudaFuncAttributeMaxDynamicSharedMemorySize, SMEM_LSTM);

    reset_kernel<<<1, 32>>>();
    embed_kernel<<<(NTOK * 300 + 255) / 256, 256>>>(iv, ov, wtab, otab);
    pad_inp_kernel<<<(NTOK * 12 + 255) / 256, 256>>>();
    pad_w_kernel<<<(2048 * DPAD + 255) / 256, 256>>>(wih0);
    chartab_kernel<<<100, 600>>>(ctab, convw);
    charconv_kernel<<<NTOK, 256>>>(chars, convb);
    crfwT_kernel<<<(NLAB * NSS * DPAD + 255) / 256, 256>>>(crfw);

    dim3 gg(16, 32);
    gemm_kernel<<<gg, 256>>>(0, (const float*)0, b0);
    lstm_kernel<<<128, 256, SMEM_LSTM>>>(0, whh0, mask);
    gemm_kernel<<<gg, 256>>>(1, wih1, b1);
    lstm_kernel<<<128, 256, SMEM_LSTM>>>(1, whh1, mask);

    em_kernel<<<NTOK, 64>>>(crfb);
    crf_kernel<<<NLAB, 32>>>(crftr, target, mask);
    reduce_kernel<<<1, 256>>>((float*)d_out);
}